// round 7
// baseline (speedup 1.0000x reference)
#include <cuda_runtime.h>
#include <cuda_bf16.h>
#include <cstdint>

// ComboSumModule: 6 tensors (N=2048, M_i, K_i) fp32, sum over axis 1.
//   x0:(2048,128,64) x1:(2048,32,32) x2:(2048,64,64)
//   x3:(2048,16,48)  x4:(2048,200,32) x5:(2048,8,8)
// Output float offsets: 0, 131072, 196608, 327680, 425984, 491520.
//
// R6: warp-sequential streaming. Each warp owns a contiguous chunk of C rows
// of one n and reads it with perfectly sequential 512B warp loads (lane k is
// fixed since Kv | 32). Row-phases (32/Kv of them) are combined with a short
// butterfly. __ldcs (evict-first) since there is zero reuse and the 168MB
// working set exceeds L2.

__device__ __forceinline__ void f4_acc(float4& a, const float4 v) {
    a.x += v.x; a.y += v.y; a.z += v.z; a.w += v.w;
}

// Warp-sequential segment: F4N = M*Kv (float4 per n), CHUNKS = chunks per n,
// CROWS = rows per chunk, ITERS = CROWS*Kv/32 (integral).
template<int F4N, int Kv, int CHUNKS, int CROWS, int ITERS>
__device__ __forceinline__ void seg_warp(const float* __restrict__ in,
                                         float* __restrict__ out,
                                         int wseg, int lane) {
    const float4* __restrict__ in4 = reinterpret_cast<const float4*>(in);
    float4* __restrict__ out4 = reinterpret_cast<float4*>(out);

    const int n = (CHUNKS == 1) ? wseg : (wseg / CHUNKS);
    const int c = (CHUNKS == 1) ? 0    : (wseg % CHUNKS);

    const float4* __restrict__ p = in4 + (size_t)n * F4N
                                       + (size_t)c * (CROWS * Kv) + lane;

    float4 a0 = make_float4(0.f, 0.f, 0.f, 0.f);
    float4 a1 = make_float4(0.f, 0.f, 0.f, 0.f);
    #pragma unroll
    for (int i = 0; i < ITERS; ++i) {
        float4 v = __ldcs(p + i * 32);        // warp reads 512B contiguous
        if (i & 1) f4_acc(a1, v); else f4_acc(a0, v);
    }
    float4 s;
    s.x = a0.x + a1.x; s.y = a0.y + a1.y;
    s.z = a0.z + a1.z; s.w = a0.w + a1.w;

    // Combine the 32/Kv row-phases (lanes equal mod Kv).
    #pragma unroll
    for (int d = Kv; d < 32; d <<= 1) {
        s.x += __shfl_xor_sync(0xFFFFFFFFu, s.x, d);
        s.y += __shfl_xor_sync(0xFFFFFFFFu, s.y, d);
        s.z += __shfl_xor_sync(0xFFFFFFFFu, s.z, d);
        s.w += __shfl_xor_sync(0xFFFFFFFFu, s.w, d);
    }
    if (CHUNKS == 1) {
        if (lane < Kv) out4[(size_t)n * Kv + lane] = s;
    } else {
        // Partial over chunk c only if CHUNKS>1? No: chunks are M-splits, so
        // partials must be summed across chunks. Avoid that: write with RED?
        // Not needed — we instead make chunks cover disjoint n? They don't.
        // => combine across chunks via atomic-free trick is not available, so
        //    chunks ARE M-splits; use red.global (deterministic enough? no).
        // Resolution: CHUNKS>1 paths below use full-M warps only (see launch
        // mapping: CROWS*CHUNKS == M and warp covers ALL rows of one n when
        // CHUNKS==1; for CHUNKS>1 we give each chunk its own warp and sum
        // with one red.global.add per lane-group leader).
        if (lane < Kv) {
            float4* q = out4 + (size_t)n * Kv + lane;
            asm volatile("red.global.add.v4.f32 [%0], {%1, %2, %3, %4};"
                         :: "l"(__cvta_generic_to_global(q)),
                            "f"(s.x), "f"(s.y), "f"(s.z), "f"(s.w)
                         : "memory");
        }
    }
}

// Per-thread style (for Kv not dividing 32 / tiny segments). One output f4
// per thread, C sequential-strided loads.
template<int M, int Kv, int C>
__device__ __forceinline__ void seg_thread(const float* __restrict__ in,
                                           float* __restrict__ out, int t) {
    const float4* __restrict__ in4 = reinterpret_cast<const float4*>(in);
    float4* __restrict__ out4 = reinterpret_cast<float4*>(out);
    const int k = t % Kv;
    const int n = t / Kv;
    const float4* __restrict__ p = in4 + (size_t)n * (size_t)(M * Kv) + k;
    float4 a0 = make_float4(0.f, 0.f, 0.f, 0.f);
    float4 a1 = make_float4(0.f, 0.f, 0.f, 0.f);
    #pragma unroll
    for (int m = 0; m < C; ++m) {
        float4 v = __ldcs(p + (size_t)m * Kv);
        if (m & 1) f4_acc(a1, v); else f4_acc(a0, v);
    }
    float4 s;
    s.x = a0.x + a1.x; s.y = a0.y + a1.y;
    s.z = a0.z + a1.z; s.w = a0.w + a1.w;
    out4[(size_t)n * Kv + k] = s;
}

// Zero-init needed for the red.global segments (seg0, seg2, seg4).
//  seg0 f4 [0, 32768)  seg2 f4 [49152, 81920)  seg4 f4 [106496, 122880)
static constexpr int ZERO_ITEMS = 32768 + 32768 + 16384;

__global__ __launch_bounds__(256)
void zero_split_regions(float* __restrict__ out) {
    int i = blockIdx.x * 256 + threadIdx.x;
    if (i >= ZERO_ITEMS) return;
    float4* o4 = reinterpret_cast<float4*>(out);
    int idx;
    if (i < 32768)       idx = i;
    else if (i < 65536)  idx = 49152  + (i - 32768);
    else                 idx = 106496 + (i - 65536);
    o4[idx] = make_float4(0.f, 0.f, 0.f, 0.f);
}

// Warp counts per segment:
//  seg0: 2048 n * 4 chunks = 8192    cum  8192
//  seg1: 2048 * 1          = 2048    cum 10240
//  seg2: 2048 * 2          = 4096    cum 14336
//  seg3: thread-style 24576 thr = 768 warps   cum 15104
//  seg4: 2048 * 5          = 10240   cum 25344
//  seg5: thread-style 4096 thr  = 128 warps   cum 25472
static constexpr int TOTAL_WARPS = 25472;            // *32 = 815104 threads
static constexpr int TOTAL_BLOCKS = TOTAL_WARPS / 8; // 3184 blocks of 256

__global__ __launch_bounds__(256, 6)
void combo_sum_kernel(const float* __restrict__ x0, const float* __restrict__ x1,
                      const float* __restrict__ x2, const float* __restrict__ x3,
                      const float* __restrict__ x4, const float* __restrict__ x5,
                      float* __restrict__ out) {
    const int j    = blockIdx.x * 256 + threadIdx.x;
    const int W    = j >> 5;
    const int lane = j & 31;

    if (W < 8192) {
        // x0: M=128,Kv=16; 4 chunks of 32 rows; 16 iters of 512B
        seg_warp<128*16, 16, 4, 32, 16>(x0, out + 0,      W,         lane);
    } else if (W < 10240) {
        // x1: M=32,Kv=8; whole n per warp; 8 iters
        seg_warp<32*8,   8,  1, 32, 8 >(x1, out + 131072, W - 8192,  lane);
    } else if (W < 14336) {
        // x2: M=64,Kv=16; 2 chunks of 32 rows; 16 iters
        seg_warp<64*16,  16, 2, 32, 16>(x2, out + 196608, W - 10240, lane);
    } else if (W < 15104) {
        // x3: M=16,Kv=12 (12 ∤ 32) -> thread style
        seg_thread<16, 12, 16>(x3, out + 327680, j - 14336 * 32);
    } else if (W < 25344) {
        // x4: M=200,Kv=8; 5 chunks of 40 rows; 10 iters
        seg_warp<200*8,  8,  5, 40, 10>(x4, out + 425984, W - 15104, lane);
    } else {
        // x5: tiny -> thread style
        seg_thread<8, 2, 8>(x5, out + 491520, j - 25344 * 32);
    }
}

extern "C" void kernel_launch(void* const* d_in, const int* in_sizes, int n_in,
                              void* d_out, int out_size) {
    const float* x0 = (const float*)d_in[0];
    const float* x1 = (const float*)d_in[1];
    const float* x2 = (const float*)d_in[2];
    const float* x3 = (const float*)d_in[3];
    const float* x4 = (const float*)d_in[4];
    const float* x5 = (const float*)d_in[5];
    float* out = (float*)d_out;

    zero_split_regions<<<(ZERO_ITEMS + 255) / 256, 256>>>(out);
    combo_sum_kernel<<<TOTAL_BLOCKS, 256>>>(x0, x1, x2, x3, x4, x5, out);
}

// round 8
// speedup vs baseline: 1.1294x; 1.1294x over previous
#include <cuda_runtime.h>
#include <cuda_bf16.h>
#include <cstdint>

// ComboSumModule: 6 tensors (N=2048, M_i, K_i) fp32, sum over axis 1.
//   x0:(2048,128,64) x1:(2048,32,32) x2:(2048,64,64)
//   x3:(2048,16,48)  x4:(2048,200,32) x5:(2048,8,8)
// Output f4 offsets: 0, 32768, 49152, 81920, 106496, 122880 (floats /4).
//
// R8: single launch. Warp-sequential 512B bursts (as R7) + block-local smem
// combine instead of global atomics (no zero pass). Each block fully owns its
// output elements. Heavy blocks placed first in the grid for tail balance.

__device__ __forceinline__ void f4_acc(float4& a, const float4 v) {
    a.x += v.x; a.y += v.y; a.z += v.z; a.w += v.w;
}

// F4N: float4 per n. Kv: K/4. NPB: n per block. NW: warps per n (NPB*NW==8).
// CF4: float4 per chunk (= F4N/NW). ITERS: ceil(CF4/32).
// TAIL: active lanes in last iter (32 if chunk is a multiple of 32 f4).
template<int F4N, int Kv, int NPB, int NW, int CF4, int ITERS, int TAIL>
__device__ __forceinline__ void seg_block(const float* __restrict__ in,
                                          float* __restrict__ out,
                                          int blk, int tid,
                                          float4 (*part)[16]) {
    const float4* __restrict__ in4 = reinterpret_cast<const float4*>(in);
    float4* __restrict__ out4 = reinterpret_cast<float4*>(out);
    const int w    = tid >> 5;
    const int lane = tid & 31;
    const int n_l  = w / NW;            // n within block
    const int c    = w % NW;            // chunk within n
    const int n    = blk * NPB + n_l;

    const float4* __restrict__ p = in4 + (size_t)n * F4N + c * CF4 + lane;

    float4 a0 = make_float4(0.f, 0.f, 0.f, 0.f);
    float4 a1 = make_float4(0.f, 0.f, 0.f, 0.f);
    #pragma unroll
    for (int i = 0; i < ITERS; ++i) {
        if (TAIL == 32 || i + 1 < ITERS || lane < TAIL) {
            float4 v = __ldcs(p + i * 32);      // warp: 512B contiguous
            if (i & 1) f4_acc(a1, v); else f4_acc(a0, v);
        }
    }
    float4 s;
    s.x = a0.x + a1.x; s.y = a0.y + a1.y;
    s.z = a0.z + a1.z; s.w = a0.w + a1.w;

    // In-warp: fold the 32/Kv row-phases (lanes equal mod Kv).
    #pragma unroll
    for (int d = Kv; d < 32; d <<= 1) {
        s.x += __shfl_xor_sync(0xFFFFFFFFu, s.x, d);
        s.y += __shfl_xor_sync(0xFFFFFFFFu, s.y, d);
        s.z += __shfl_xor_sync(0xFFFFFFFFu, s.z, d);
        s.w += __shfl_xor_sync(0xFFFFFFFFu, s.w, d);
    }

    if (NW == 1) {
        if (lane < Kv) out4[(size_t)n * Kv + lane] = s;
    } else {
        if (lane < Kv) part[w][lane] = s;
        __syncthreads();
        if (tid < NPB * Kv) {                   // NPB*Kv <= 32
            const int nl = tid / Kv;
            const int k  = tid % Kv;
            float4 t = part[nl * NW][k];
            #pragma unroll
            for (int ww = 1; ww < NW; ++ww)
                f4_acc(t, part[nl * NW + ww][k]);
            out4[(size_t)(blk * NPB + nl) * Kv + k] = t;
        }
    }
}

// Per-thread style for Kv not dividing 32 / tiny segments.
template<int M, int Kv, int C>
__device__ __forceinline__ void seg_thread(const float* __restrict__ in,
                                           float* __restrict__ out, int t) {
    const float4* __restrict__ in4 = reinterpret_cast<const float4*>(in);
    float4* __restrict__ out4 = reinterpret_cast<float4*>(out);
    const int k = t % Kv;
    const int n = t / Kv;
    const float4* __restrict__ p = in4 + (size_t)n * (size_t)(M * Kv) + k;
    float4 a0 = make_float4(0.f, 0.f, 0.f, 0.f);
    float4 a1 = make_float4(0.f, 0.f, 0.f, 0.f);
    #pragma unroll
    for (int m = 0; m < C; ++m) {
        float4 v = __ldcs(p + (size_t)m * Kv);
        if (m & 1) f4_acc(a1, v); else f4_acc(a0, v);
    }
    float4 s;
    s.x = a0.x + a1.x; s.y = a0.y + a1.y;
    s.z = a0.z + a1.z; s.w = a0.w + a1.w;
    out4[(size_t)n * Kv + k] = s;
}

// Block layout (heavy blocks first for tail balance):
//  seg3: [0, 96)        thread-style, 64KB/block  (2048n*12 = 24576 items)
//  seg0: [96, 2144)     NPB=1 NW=8 CF4=256 ITERS=8          32KB/block
//  seg2: [2144, 3168)   NPB=2 NW=4 CF4=256 ITERS=8          32KB/block
//  seg1: [3168, 3424)   NPB=8 NW=1 CF4=256 ITERS=8          32KB/block
//  seg4: [3424, 5472)   NPB=1 NW=8 CF4=200 ITERS=7 TAIL=8   25.6KB/block
//  seg5: [5472, 5488)   thread-style (4096 items)
static constexpr int TOTAL_BLOCKS = 5488;

__global__ __launch_bounds__(256, 6)
void combo_sum_kernel(const float* __restrict__ x0, const float* __restrict__ x1,
                      const float* __restrict__ x2, const float* __restrict__ x3,
                      const float* __restrict__ x4, const float* __restrict__ x5,
                      float* __restrict__ out) {
    __shared__ float4 part[8][16];
    const int blk = blockIdx.x;
    const int tid = threadIdx.x;

    if (blk < 96) {
        seg_thread<16, 12, 16>(x3, out + 327680, blk * 256 + tid);
    } else if (blk < 2144) {
        seg_block<2048, 16, 1, 8, 256, 8, 32>(x0, out + 0,      blk - 96,   tid, part);
    } else if (blk < 3168) {
        seg_block<1024, 16, 2, 4, 256, 8, 32>(x2, out + 196608, blk - 2144, tid, part);
    } else if (blk < 3424) {
        seg_block<256,  8,  8, 1, 256, 8, 32>(x1, out + 131072, blk - 3168, tid, part);
    } else if (blk < 5472) {
        seg_block<1600, 8,  1, 8, 200, 7, 8 >(x4, out + 425984, blk - 3424, tid, part);
    } else {
        seg_thread<8, 2, 8>(x5, out + 491520, (blk - 5472) * 256 + tid);
    }
}

extern "C" void kernel_launch(void* const* d_in, const int* in_sizes, int n_in,
                              void* d_out, int out_size) {
    const float* x0 = (const float*)d_in[0];
    const float* x1 = (const float*)d_in[1];
    const float* x2 = (const float*)d_in[2];
    const float* x3 = (const float*)d_in[3];
    const float* x4 = (const float*)d_in[4];
    const float* x5 = (const float*)d_in[5];
    float* out = (float*)d_out;

    combo_sum_kernel<<<TOTAL_BLOCKS, 256>>>(x0, x1, x2, x3, x4, x5, out);
}